// round 15
// baseline (speedup 1.0000x reference)
#include <cuda_runtime.h>
#include <cuda_fp16.h>
#include <math.h>

constexpr int  B_ = 256, T_ = 512, I_ = 128, H_ = 256, L_ = 64, P_ = 50;
constexpr long BT = (long)B_ * T_;
constexpr long PMU_OFF = BT * I_, PLV_OFF = PMU_OFF + BT * L_;
constexpr long QMU_OFF = PLV_OFF + BT * L_, QLV_OFF = QMU_OFF + BT * L_;
constexpr int CHUNK = 128, NCHUNK = T_ / CHUNK;

__device__ float g_H[BT * H_];
__device__ float g_Z[BT * L_];
__device__ float g_preQM[BT * P_];
__device__ float g_preQL[BT * P_];
__device__ float g_preH[BT * P_];

using u64 = unsigned long long;
__device__ __forceinline__ u64 pk(float x, float y) {
    u64 r; asm("mov.b64 %0,{%1,%2};" : "=l"(r) : "f"(x), "f"(y)); return r;
}
__device__ __forceinline__ float2 up(u64 v) {
    float2 f; asm("mov.b64 {%0,%1},%2;" : "=f"(f.x), "=f"(f.y) : "l"(v)); return f;
}
__device__ __forceinline__ u64 f2fma(u64 a, u64 b, u64 c) {
    u64 d; asm("fma.rn.f32x2 %0,%1,%2,%3;" : "=l"(d) : "l"(a), "l"(b), "l"(c)); return d;
}
__device__ __forceinline__ float hsum(u64 v) { float2 f = up(v); return f.x + f.y; }
using ull2 = ulonglong2;

// ===================== Phase A =====================
constexpr int ROWS_A = 64, XS = 132;
constexpr size_t SMEM_PRE = (size_t)(ROWS_A * XS + 192) * sizeof(float);

__global__ __launch_bounds__(256) void k_pre(
    const float* __restrict__ x,
    const float* __restrict__ Wqm1, const float* __restrict__ bqm1,
    const float* __restrict__ Wql1, const float* __restrict__ bql1,
    const float* __restrict__ Wh1,  const float* __restrict__ bh1)
{
    extern __shared__ float sm[];
    float* sx = sm; float* sb = sx + ROWS_A * XS;
    const int tid = threadIdx.x;
    const long bt0 = (long)blockIdx.x * ROWS_A;

    for (int idx = tid; idx < ROWS_A * I_; idx += 256)
        sx[(idx >> 7) * XS + (idx & 127)] = x[bt0 * I_ + idx];
    if (tid < P_) { sb[tid] = bqm1[tid]; sb[64 + tid] = bql1[tid]; sb[128 + tid] = bh1[tid]; }
    __syncthreads();

    for (int task = tid; task < 480; task += 256) {
        int og = task >> 4, g = task & 15;
        const ull2* w4[5]; int ms[5], js[5];
        #pragma unroll
        for (int q = 0; q < 5; q++) {
            int o = og * 5 + q, m = o / P_, j = o - m * P_;
            ms[q] = m; js[q] = j;
            const float* base = (m == 0) ? (Wqm1 + j * 384) : (m == 1) ? (Wql1 + j * 384) : (Wh1 + j * 448);
            w4[q] = (const ull2*)base;
        }
        const ull2* x4[4];
        #pragma unroll
        for (int rr = 0; rr < 4; rr++) x4[rr] = (const ull2*)(sx + (rr * 16 + g) * XS);
        u64 acc[5][4];
        #pragma unroll
        for (int q = 0; q < 5; q++)
            #pragma unroll
            for (int rr = 0; rr < 4; rr++) acc[q][rr] = 0;
        #pragma unroll 4
        for (int k = 0; k < I_ / 4; k++) {
            ull2 xv[4];
            #pragma unroll
            for (int rr = 0; rr < 4; rr++) xv[rr] = x4[rr][k];
            #pragma unroll
            for (int q = 0; q < 5; q++) {
                ull2 wv = w4[q][k];
                #pragma unroll
                for (int rr = 0; rr < 4; rr++) {
                    acc[q][rr] = f2fma(wv.x, xv[rr].x, acc[q][rr]);
                    acc[q][rr] = f2fma(wv.y, xv[rr].y, acc[q][rr]);
                }
            }
        }
        #pragma unroll
        for (int q = 0; q < 5; q++) {
            int m = ms[q], j = js[q];
            float* dst = (m == 0) ? g_preQM : (m == 1) ? g_preQL : g_preH;
            float bias = sb[m * 64 + j];
            #pragma unroll
            for (int rr = 0; rr < 4; rr++)
                dst[(bt0 + rr * 16 + g) * P_ + j] = bias + hsum(acc[q][rr]);
        }
    }
}

// ===================== Phase B (chunked, 320 threads) =====================
constexpr int WS = 260;
constexpr int O_W1 = 0, O_W2T = O_W1 + 3 * P_ * WS, O_B2 = O_W2T + 50 * 128;
constexpr int O_BH2 = O_B2 + 128, O_H = O_BH2 + 256, O_A1 = O_H + 4 * WS;
constexpr int O_VH = O_A1 + 200, O_AH = O_VH + 104, O_Z = O_AH + 104;
constexpr size_t SMEM_SEQ = (size_t)(O_Z + 136) * sizeof(float);
constexpr int NT = 320;

__global__ __launch_bounds__(NT, 1) void k_seq(
    const float* __restrict__ hidden, const float* __restrict__ noise,
    const float* __restrict__ Wqm1, const float* __restrict__ Wqm2, const float* __restrict__ bqm2,
    const float* __restrict__ Wql1, const float* __restrict__ Wql2, const float* __restrict__ bql2,
    const float* __restrict__ Wh1,  const float* __restrict__ Wh2,  const float* __restrict__ bh2,
    float* __restrict__ out, int t0, int t1)
{
    extern __shared__ float sm[];
    float* sW1 = sm + O_W1; float* sW2t = sm + O_W2T; float* sb2 = sm + O_B2;
    float* sbh2 = sm + O_BH2; float* sH = sm + O_H; float* sA1 = sm + O_A1;
    float* sVH = sm + O_VH; float* sAH = sm + O_AH; float* sZ = sm + O_Z;

    const int tid = threadIdx.x;
    const int r0 = blockIdx.x * 2;

    for (int idx = tid; idx < P_ * H_; idx += NT) {
        int j = idx >> 8, k = idx & 255;
        sW1[j * WS + k] = Wqm1[j * 384 + 128 + k];
        sW1[(P_ + j) * WS + k] = Wql1[j * 384 + 128 + k];
        sW1[(2 * P_ + j) * WS + k] = Wh1[j * 448 + 128 + k];
    }
    for (int idx = tid; idx < L_ * P_; idx += NT) {
        int n = idx / P_, j = idx - n * P_;
        sW2t[j * 128 + 2 * n] = Wqm2[n * P_ + j];
        sW2t[j * 128 + 2 * n + 1] = Wql2[n * P_ + j];
    }
    if (tid < L_) { sb2[2 * tid] = bqm2[tid]; sb2[2 * tid + 1] = bql2[tid]; }
    if (tid < H_) sbh2[tid] = bh2[tid];
    for (int idx = tid; idx < 2 * H_; idx += NT) {
        int r = idx >> 8, k = idx & 255;
        sH[r * WS + k] = (t0 == 0) ? hidden[(r0 + r) * H_ + k]
                                   : g_H[((long)(r0 + r) * T_ + t0) * H_ + k];
    }
    if (tid == 0) { sAH[50] = sAH[51] = sAH[102] = sAH[103] = 0.f; }

    __half2 wh2c[52];
    if (tid < 256) {
        int kp = tid & 127;
        #pragma unroll
        for (int j = 0; j < 50; j++)
            wh2c[j] = __floats2half2_rn(Wh2[2 * kp * P_ + j], Wh2[(2 * kp + 1) * P_ + j]);
        wh2c[50] = wh2c[51] = __floats2half2_rn(0.f, 0.f);
    }
    __half2 wzc[32];
    if (tid < 100) {
        int j = tid % 50;
        #pragma unroll
        for (int i = 0; i < 32; i++)
            wzc[i] = __floats2half2_rn(Wh1[j * 448 + 384 + 2 * i], Wh1[j * 448 + 384 + 2 * i + 1]);
    }
    __syncthreads();

    int cb = 0;
    for (int t = t0; t < t1; t++) {
        const long bt0v = (long)r0 * T_ + t, bt1v = bt0v + T_;
        float e = 0.f;
        if (tid < 256 && (tid & 1) == 0) {
            int r = tid >> 7, n = (tid >> 1) & 63;
            e = noise[(r ? bt1v : bt0v) * L_ + n];
        }

        // ---- s1: 300 threads, (row, k-half); shfl pair combine ----
        if (tid < 300) {
            int kh = tid & 1, row = tid >> 1;      // row 0..149
            const ull2* w = (const ull2*)(sW1 + row * WS + kh * 128);
            const ull2* h0 = (const ull2*)(sH + (cb * 2) * WS + kh * 128);
            const ull2* h1 = (const ull2*)(sH + (cb * 2 + 1) * WS + kh * 128);
            u64 a00 = 0, a01 = 0, a10 = 0, a11 = 0;
            #pragma unroll 8
            for (int k = 0; k < 32; k++) {
                ull2 wv = w[k], hv0 = h0[k], hv1 = h1[k];
                a00 = f2fma(wv.x, hv0.x, a00); a01 = f2fma(wv.y, hv0.y, a01);
                a10 = f2fma(wv.x, hv1.x, a10); a11 = f2fma(wv.y, hv1.y, a11);
            }
            float s0 = hsum(a00) + hsum(a01);
            float s1v = hsum(a10) + hsum(a11);
            unsigned mask = (tid < 288) ? 0xFFFFFFFFu : 0x00000FFFu;
            s0  += __shfl_xor_sync(mask, s0, 1);
            s1v += __shfl_xor_sync(mask, s1v, 1);
            if (kh == 0) {
                int m = row / 50, j = row - m * 50;
                const float* pre = (m == 0) ? g_preQM : (m == 1) ? g_preQL : g_preH;
                s0  += pre[bt0v * P_ + j];
                s1v += pre[bt1v * P_ + j];
                if (m == 0)      { sA1[j * 4 + 0] = fmaxf(s0, 0.f); sA1[j * 4 + 2] = fmaxf(s1v, 0.f); }
                else if (m == 1) { sA1[j * 4 + 1] = fmaxf(s0, 0.f); sA1[j * 4 + 3] = fmaxf(s1v, 0.f); }
                else             { sVH[j] = s0; sVH[52 + j] = s1v; }
            }
        } else {
            for (int idx = tid - 300; idx < 2 * H_; idx += 20) {
                int r = idx >> 8, k = idx & 255;
                g_H[(r ? bt1v : bt0v) * H_ + k] = sH[(cb * 2 + r) * WS + k];
            }
        }
        __syncthreads();

        // ---- s2: 256 threads, (r, n, j-half); shfl pair combine ----
        if (tid < 256) {
            int jh = tid & 1, n = (tid >> 1) & 63, r = tid >> 7;
            long bt = r ? bt1v : bt0v;
            u64 acc = jh ? 0ULL : pk(sb2[2 * n], sb2[2 * n + 1]);
            const u64* wp = (const u64*)(sW2t) + jh * 25 * 64 + n;
            const u64* ap = (const u64*)(sA1 + 2 * r) + jh * 25 * 2;
            #pragma unroll
            for (int j = 0; j < 25; j++)
                acc = f2fma(wp[j * 64], ap[j * 2], acc);
            float2 q = up(acc);
            q.x += __shfl_xor_sync(0xFFFFFFFFu, q.x, 1);
            q.y += __shfl_xor_sync(0xFFFFFFFFu, q.y, 1);
            if (jh == 0) {
                out[QMU_OFF + bt * L_ + n] = q.x;
                out[QLV_OFF + bt * L_ + n] = q.y;
                float z = q.x + __expf(0.5f * q.y) * e;
                sZ[r * 68 + n] = z;
                g_Z[bt * L_ + n] = z;
            }
        }
        __syncthreads();

        // ---- s3: add z-part (reg fp16 Wz), relu ----
        if (tid < 100) {
            int r = tid / 50, j = tid - r * 50;
            const float4* z4 = (const float4*)(sZ + r * 68);
            u64 acc1 = 0, acc2 = 0;
            #pragma unroll
            for (int i = 0; i < 16; i++) {
                float4 z = z4[i];
                float2 wa = __half22float2(wzc[2 * i]);
                float2 wb = __half22float2(wzc[2 * i + 1]);
                acc1 = f2fma(pk(wa.x, wa.y), pk(z.x, z.y), acc1);
                acc2 = f2fma(pk(wb.x, wb.y), pk(z.z, z.w), acc2);
            }
            sAH[r * 52 + j] = fmaxf(sVH[r * 52 + j] + hsum(acc1) + hsum(acc2), 0.f);
        }
        __syncthreads();

        // ---- s4: 256 threads, 2 h-outputs each (reg fp16 Wh2) ----
        if (tid < 256) {
            int r = tid >> 7, kp = tid & 127;
            const float4* a4 = (const float4*)(sAH + r * 52);
            float2 bb = *(const float2*)(sbh2 + 2 * kp);
            u64 acc = pk(bb.x, bb.y), acc2 = 0;
            #pragma unroll
            for (int q = 0; q < 13; q++) {
                float4 av = a4[q];
                float2 w0 = __half22float2(wh2c[4 * q]);     acc  = f2fma(pk(w0.x, w0.y), pk(av.x, av.x), acc);
                float2 w1 = __half22float2(wh2c[4 * q + 1]); acc2 = f2fma(pk(w1.x, w1.y), pk(av.y, av.y), acc2);
                float2 w2 = __half22float2(wh2c[4 * q + 2]); acc  = f2fma(pk(w2.x, w2.y), pk(av.z, av.z), acc);
                float2 w3 = __half22float2(wh2c[4 * q + 3]); acc2 = f2fma(pk(w3.x, w3.y), pk(av.w, av.w), acc2);
            }
            float2 r1 = up(acc), r2 = up(acc2);
            int nb = cb ^ 1;
            *(float2*)(sH + (nb * 2 + r) * WS + 2 * kp) = make_float2(r1.x + r2.x, r1.y + r2.y);
        }
        __syncthreads();
        cb ^= 1;
    }

    if (t1 < T_) {
        for (int idx = tid; idx < 2 * H_; idx += NT) {
            int r = idx >> 8, k = idx & 255;
            g_H[((long)(r0 + r) * T_ + t1) * H_ + k] = sH[(cb * 2 + r) * WS + k];
        }
    }
}

// ===================== Phase C1 (chunked) =====================
constexpr int ROWS_P = 32;
constexpr int PO_W2 = 0, PO_B1 = PO_W2 + 2 * L_ * P_, PO_B2 = PO_B1 + 128;
constexpr int PO_H = PO_B2 + 128, PO_A = PO_H + ROWS_P * WS;
constexpr size_t SMEM_P = (size_t)(PO_A + 2 * ROWS_P * 52) * sizeof(float);

__global__ __launch_bounds__(256) void k_pbranch(
    const float* __restrict__ Wpm1, const float* __restrict__ bpm1,
    const float* __restrict__ Wpm2, const float* __restrict__ bpm2,
    const float* __restrict__ Wpl1, const float* __restrict__ bpl1,
    const float* __restrict__ Wpl2, const float* __restrict__ bpl2,
    float* __restrict__ out, int t0)
{
    extern __shared__ float sm[];
    float* sW2 = sm + PO_W2; float* sb1 = sm + PO_B1;
    float* sb2 = sm + PO_B2; float* sh = sm + PO_H; float* sa = sm + PO_A;
    const int tid = threadIdx.x;
    const int b = blockIdx.x >> 2, seg = blockIdx.x & 3;
    const long bt0 = (long)b * T_ + t0 + seg * ROWS_P;

    for (int idx = tid; idx < L_ * P_; idx += 256) {
        sW2[idx] = Wpm2[idx]; sW2[L_ * P_ + idx] = Wpl2[idx];
    }
    if (tid < P_) { sb1[tid] = bpm1[tid]; sb1[64 + tid] = bpl1[tid]; }
    if (tid < L_) { sb2[tid] = bpm2[tid]; sb2[64 + tid] = bpl2[tid]; }
    for (int idx = tid; idx < ROWS_P * H_; idx += 256)
        sh[(idx >> 8) * WS + (idx & 255)] = g_H[bt0 * H_ + idx];
    __syncthreads();

    if (tid < 100) {
        int op = tid >> 2, g = tid & 3;
        const ull2* w4[4]; const ull2* h4[8];
        #pragma unroll
        for (int q = 0; q < 4; q++) {
            int o = op * 4 + q, m = o / P_, j = o - m * P_;
            w4[q] = (const ull2*)((m == 0 ? Wpm1 : Wpl1) + j * H_);
        }
        #pragma unroll
        for (int rr = 0; rr < 8; rr++) h4[rr] = (const ull2*)(sh + (rr * 4 + g) * WS);
        u64 acc[4][8];
        #pragma unroll
        for (int q = 0; q < 4; q++)
            #pragma unroll
            for (int rr = 0; rr < 8; rr++) acc[q][rr] = 0;
        #pragma unroll 4
        for (int k = 0; k < H_ / 4; k++) {
            ull2 hv[8];
            #pragma unroll
            for (int rr = 0; rr < 8; rr++) hv[rr] = h4[rr][k];
            #pragma unroll
            for (int q = 0; q < 4; q++) {
                ull2 wv = w4[q][k];
                #pragma unroll
                for (int rr = 0; rr < 8; rr++) {
                    acc[q][rr] = f2fma(wv.x, hv[rr].x, acc[q][rr]);
                    acc[q][rr] = f2fma(wv.y, hv[rr].y, acc[q][rr]);
                }
            }
        }
        #pragma unroll
        for (int q = 0; q < 4; q++) {
            int o = op * 4 + q, m = o / P_, j = o - m * P_;
            float bias = sb1[m * 64 + j];
            #pragma unroll
            for (int rr = 0; rr < 8; rr++)
                sa[(m * ROWS_P + rr * 4 + g) * 52 + j] = fmaxf(bias + hsum(acc[q][rr]), 0.f);
        }
    }
    __syncthreads();

    for (int task = tid; task < 2 * ROWS_P * L_; task += 256) {
        int m = task / (ROWS_P * L_); int rn = task - m * ROWS_P * L_;
        int r = rn >> 6, n = rn & 63;
        const float* w = sW2 + (m * L_ + n) * P_;
        const float* a = sa + (m * ROWS_P + r) * 52;
        float acc = sb2[m * 64 + n];
        #pragma unroll
        for (int j = 0; j < P_; j++) acc += w[j] * a[j];
        out[((m == 0) ? PMU_OFF : PLV_OFF) + (bt0 + r) * L_ + n] = acc;
    }
}

// ===================== Phase C2 (chunked) =====================
constexpr int ROWS_O = 32;
constexpr int OO_H = 0, OO_Z = OO_H + ROWS_O * WS, OO_B = OO_Z + ROWS_O * 68;
constexpr size_t SMEM_O = (size_t)(OO_B + 128) * sizeof(float);

__global__ __launch_bounds__(128) void k_out(
    const float* __restrict__ Wo, const float* __restrict__ bo, float* __restrict__ out, int t0)
{
    extern __shared__ float sm[];
    float* sh = sm + OO_H; float* sz = sm + OO_Z; float* sbo = sm + OO_B;
    const int tid = threadIdx.x;
    const int b = blockIdx.x >> 2, seg = blockIdx.x & 3;
    const long bt0 = (long)b * T_ + t0 + seg * ROWS_O;

    for (int idx = tid; idx < ROWS_O * H_; idx += 128)
        sh[(idx >> 8) * WS + (idx & 255)] = g_H[bt0 * H_ + idx];
    for (int idx = tid; idx < ROWS_O * L_; idx += 128)
        sz[(idx >> 6) * 68 + (idx & 63)] = g_Z[bt0 * L_ + idx];
    if (tid < I_) sbo[tid] = bo[tid];
    __syncthreads();

    {
        int ig = tid >> 2, g = tid & 3;
        const ull2* w4[4]; const ull2* h4[8]; const ull2* z4[8];
        #pragma unroll
        for (int q = 0; q < 4; q++) w4[q] = (const ull2*)(Wo + (ig * 4 + q) * 320);
        #pragma unroll
        for (int rr = 0; rr < 8; rr++) {
            h4[rr] = (const ull2*)(sh + (rr * 4 + g) * WS);
            z4[rr] = (const ull2*)(sz + (rr * 4 + g) * 68);
        }
        u64 acc[4][8];
        #pragma unroll
        for (int q = 0; q < 4; q++)
            #pragma unroll
            for (int rr = 0; rr < 8; rr++) acc[q][rr] = 0;
        #pragma unroll 4
        for (int k = 0; k < H_ / 4; k++) {
            ull2 hv[8];
            #pragma unroll
            for (int rr = 0; rr < 8; rr++) hv[rr] = h4[rr][k];
            #pragma unroll
            for (int q = 0; q < 4; q++) {
                ull2 wv = w4[q][k];
                #pragma unroll
                for (int rr = 0; rr < 8; rr++) {
                    acc[q][rr] = f2fma(wv.x, hv[rr].x, acc[q][rr]);
                    acc[q][rr] = f2fma(wv.y, hv[rr].y, acc[q][rr]);
                }
            }
        }
        #pragma unroll
        for (int k = 0; k < L_ / 4; k++) {
            ull2 zv[8];
            #pragma unroll
            for (int rr = 0; rr < 8; rr++) zv[rr] = z4[rr][k];
            #pragma unroll
            for (int q = 0; q < 4; q++) {
                ull2 wv = w4[q][64 + k];
                #pragma unroll
                for (int rr = 0; rr < 8; rr++) {
                    acc[q][rr] = f2fma(wv.x, zv[rr].x, acc[q][rr]);
                    acc[q][rr] = f2fma(wv.y, zv[rr].y, acc[q][rr]);
                }
            }
        }
        #pragma unroll
        for (int q = 0; q < 4; q++) {
            int i = ig * 4 + q; float bias = sbo[i];
            #pragma unroll
            for (int rr = 0; rr < 8; rr++) {
                float v = bias + hsum(acc[q][rr]);
                out[(bt0 + rr * 4 + g) * I_ + i] = 1.0f / (1.0f + __expf(-v));
            }
        }
    }
}

// ===================== launch: pipelined chunks =====================
extern "C" void kernel_launch(void* const* d_in, const int* in_sizes, int n_in,
                              void* d_out, int out_size) {
    const float* x = (const float*)d_in[0];
    const float* hidden = (const float*)d_in[1];
    const float* noise = (const float*)d_in[2];
    const float* Wpm1 = (const float*)d_in[3];  const float* bpm1 = (const float*)d_in[4];
    const float* Wpm2 = (const float*)d_in[5];  const float* bpm2 = (const float*)d_in[6];
    const float* Wpl1 = (const float*)d_in[7];  const float* bpl1 = (const float*)d_in[8];
    const float* Wpl2 = (const float*)d_in[9];  const float* bpl2 = (const float*)d_in[10];
    const float* Wqm1 = (const float*)d_in[11]; const float* bqm1 = (const float*)d_in[12];
    const float* Wqm2 = (const float*)d_in[13]; const float* bqm2 = (const float*)d_in[14];
    const float* Wql1 = (const float*)d_in[15]; const float* bql1 = (const float*)d_in[16];
    const float* Wql2 = (const float*)d_in[17]; const float* bql2 = (const float*)d_in[18];
    const float* Wh1 = (const float*)d_in[19];  const float* bh1 = (const float*)d_in[20];
    const float* Wh2 = (const float*)d_in[21];  const float* bh2 = (const float*)d_in[22];
    const float* Wo = (const float*)d_in[23];   const float* bo = (const float*)d_in[24];
    float* out = (float*)d_out;

    cudaFuncSetAttribute(k_pre, cudaFuncAttributeMaxDynamicSharedMemorySize, (int)SMEM_PRE);
    cudaFuncSetAttribute(k_seq, cudaFuncAttributeMaxDynamicSharedMemorySize, (int)SMEM_SEQ);
    cudaFuncSetAttribute(k_pbranch, cudaFuncAttributeMaxDynamicSharedMemorySize, (int)SMEM_P);
    cudaFuncSetAttribute(k_out, cudaFuncAttributeMaxDynamicSharedMemorySize, (int)SMEM_O);

    cudaStream_t s1;
    cudaStreamCreateWithFlags(&s1, cudaStreamNonBlocking);
    cudaEvent_t evA[NCHUNK], evB;
    for (int c = 0; c < NCHUNK; c++) cudaEventCreateWithFlags(&evA[c], cudaEventDisableTiming);
    cudaEventCreateWithFlags(&evB, cudaEventDisableTiming);

    k_pre<<<(int)(BT / ROWS_A), 256, SMEM_PRE>>>(x, Wqm1, bqm1, Wql1, bql1, Wh1, bh1);

    const int gridC = B_ * (CHUNK / ROWS_P);
    for (int c = 0; c < NCHUNK; c++) {
        int t0 = c * CHUNK, t1 = t0 + CHUNK;
        k_seq<<<B_ / 2, NT, SMEM_SEQ>>>(hidden, noise, Wqm1, Wqm2, bqm2,
                                        Wql1, Wql2, bql2, Wh1, Wh2, bh2, out, t0, t1);
        cudaEventRecord(evA[c], 0);
        cudaStreamWaitEvent(s1, evA[c], 0);
        k_pbranch<<<gridC, 256, SMEM_P, s1>>>(Wpm1, bpm1, Wpm2, bpm2,
                                              Wpl1, bpl1, Wpl2, bpl2, out, t0);
        k_out<<<gridC, 128, SMEM_O, s1>>>(Wo, bo, out, t0);
    }
    cudaEventRecord(evB, s1);
    cudaStreamWaitEvent(0, evB, 0);
}

// round 16
// speedup vs baseline: 1.2262x; 1.2262x over previous
#include <cuda_runtime.h>
#include <cuda_fp16.h>
#include <math.h>

constexpr int  B_ = 256, T_ = 512, I_ = 128, H_ = 256, L_ = 64, P_ = 50;
constexpr long BT = (long)B_ * T_;
constexpr long PMU_OFF = BT * I_, PLV_OFF = PMU_OFF + BT * L_;
constexpr long QMU_OFF = PLV_OFF + BT * L_, QLV_OFF = QMU_OFF + BT * L_;
constexpr int CHUNK = 128, NCHUNK = T_ / CHUNK;

__device__ float g_H[BT * H_];
__device__ float g_Z[BT * L_];
__device__ float g_preQM[BT * P_];
__device__ float g_preQL[BT * P_];
__device__ float g_preH[BT * P_];

using u64 = unsigned long long;
__device__ __forceinline__ u64 pk(float x, float y) {
    u64 r; asm("mov.b64 %0,{%1,%2};" : "=l"(r) : "f"(x), "f"(y)); return r;
}
__device__ __forceinline__ float2 up(u64 v) {
    float2 f; asm("mov.b64 {%0,%1},%2;" : "=f"(f.x), "=f"(f.y) : "l"(v)); return f;
}
__device__ __forceinline__ u64 f2fma(u64 a, u64 b, u64 c) {
    u64 d; asm("fma.rn.f32x2 %0,%1,%2,%3;" : "=l"(d) : "l"(a), "l"(b), "l"(c)); return d;
}
__device__ __forceinline__ float hsum(u64 v) { float2 f = up(v); return f.x + f.y; }
using ull2 = ulonglong2;

// ===================== Phase A =====================
constexpr int ROWS_A = 64, XS = 132;
constexpr size_t SMEM_PRE = (size_t)(ROWS_A * XS + 192) * sizeof(float);

__global__ __launch_bounds__(256) void k_pre(
    const float* __restrict__ x,
    const float* __restrict__ Wqm1, const float* __restrict__ bqm1,
    const float* __restrict__ Wql1, const float* __restrict__ bql1,
    const float* __restrict__ Wh1,  const float* __restrict__ bh1)
{
    extern __shared__ float sm[];
    float* sx = sm; float* sb = sx + ROWS_A * XS;
    const int tid = threadIdx.x;
    const long bt0 = (long)blockIdx.x * ROWS_A;

    for (int idx = tid; idx < ROWS_A * I_; idx += 256)
        sx[(idx >> 7) * XS + (idx & 127)] = x[bt0 * I_ + idx];
    if (tid < P_) { sb[tid] = bqm1[tid]; sb[64 + tid] = bql1[tid]; sb[128 + tid] = bh1[tid]; }
    __syncthreads();

    for (int task = tid; task < 480; task += 256) {
        int og = task >> 4, g = task & 15;
        const ull2* w4[5]; int ms[5], js[5];
        #pragma unroll
        for (int q = 0; q < 5; q++) {
            int o = og * 5 + q, m = o / P_, j = o - m * P_;
            ms[q] = m; js[q] = j;
            const float* base = (m == 0) ? (Wqm1 + j * 384) : (m == 1) ? (Wql1 + j * 384) : (Wh1 + j * 448);
            w4[q] = (const ull2*)base;
        }
        const ull2* x4[4];
        #pragma unroll
        for (int rr = 0; rr < 4; rr++) x4[rr] = (const ull2*)(sx + (rr * 16 + g) * XS);
        u64 acc[5][4];
        #pragma unroll
        for (int q = 0; q < 5; q++)
            #pragma unroll
            for (int rr = 0; rr < 4; rr++) acc[q][rr] = 0;
        #pragma unroll 4
        for (int k = 0; k < I_ / 4; k++) {
            ull2 xv[4];
            #pragma unroll
            for (int rr = 0; rr < 4; rr++) xv[rr] = x4[rr][k];
            #pragma unroll
            for (int q = 0; q < 5; q++) {
                ull2 wv = w4[q][k];
                #pragma unroll
                for (int rr = 0; rr < 4; rr++) {
                    acc[q][rr] = f2fma(wv.x, xv[rr].x, acc[q][rr]);
                    acc[q][rr] = f2fma(wv.y, xv[rr].y, acc[q][rr]);
                }
            }
        }
        #pragma unroll
        for (int q = 0; q < 5; q++) {
            int m = ms[q], j = js[q];
            float* dst = (m == 0) ? g_preQM : (m == 1) ? g_preQL : g_preH;
            float bias = sb[m * 64 + j];
            #pragma unroll
            for (int rr = 0; rr < 4; rr++)
                dst[(bt0 + rr * 16 + g) * P_ + j] = bias + hsum(acc[q][rr]);
        }
    }
}

// ===================== Phase B (chunked, 320 threads) =====================
constexpr int WS = 260;
constexpr int O_W1 = 0, O_W2T = O_W1 + 3 * P_ * WS, O_B2 = O_W2T + 50 * 128;
constexpr int O_BH2 = O_B2 + 128, O_H = O_BH2 + 256, O_A1 = O_H + 4 * WS;
constexpr int O_VH = O_A1 + 200, O_AH = O_VH + 104, O_Z = O_AH + 104;
constexpr size_t SMEM_SEQ = (size_t)(O_Z + 136) * sizeof(float);
constexpr int NT = 320;

__global__ __launch_bounds__(NT, 1) void k_seq(
    const float* __restrict__ hidden, const float* __restrict__ noise,
    const float* __restrict__ Wqm1, const float* __restrict__ Wqm2, const float* __restrict__ bqm2,
    const float* __restrict__ Wql1, const float* __restrict__ Wql2, const float* __restrict__ bql2,
    const float* __restrict__ Wh1,  const float* __restrict__ Wh2,  const float* __restrict__ bh2,
    float* __restrict__ out, int t0, int t1)
{
    extern __shared__ float sm[];
    float* sW1 = sm + O_W1; float* sW2t = sm + O_W2T; float* sb2 = sm + O_B2;
    float* sbh2 = sm + O_BH2; float* sH = sm + O_H; float* sA1 = sm + O_A1;
    float* sVH = sm + O_VH; float* sAH = sm + O_AH; float* sZ = sm + O_Z;

    const int tid = threadIdx.x;
    const int r0 = blockIdx.x * 2;

    for (int idx = tid; idx < P_ * H_; idx += NT) {
        int j = idx >> 8, k = idx & 255;
        sW1[j * WS + k] = Wqm1[j * 384 + 128 + k];
        sW1[(P_ + j) * WS + k] = Wql1[j * 384 + 128 + k];
        sW1[(2 * P_ + j) * WS + k] = Wh1[j * 448 + 128 + k];
    }
    for (int idx = tid; idx < L_ * P_; idx += NT) {
        int n = idx / P_, j = idx - n * P_;
        sW2t[j * 128 + 2 * n] = Wqm2[n * P_ + j];
        sW2t[j * 128 + 2 * n + 1] = Wql2[n * P_ + j];
    }
    if (tid < L_) { sb2[2 * tid] = bqm2[tid]; sb2[2 * tid + 1] = bql2[tid]; }
    if (tid < H_) sbh2[tid] = bh2[tid];
    for (int idx = tid; idx < 2 * H_; idx += NT) {
        int r = idx >> 8, k = idx & 255;
        sH[r * WS + k] = (t0 == 0) ? hidden[(r0 + r) * H_ + k]
                                   : g_H[((long)(r0 + r) * T_ + t0) * H_ + k];
    }
    if (tid == 0) { sAH[50] = sAH[51] = sAH[102] = sAH[103] = 0.f; }

    __half2 wh2c[52];
    if (tid < 256) {
        int kp = tid & 127;
        #pragma unroll
        for (int j = 0; j < 50; j++)
            wh2c[j] = __floats2half2_rn(Wh2[2 * kp * P_ + j], Wh2[(2 * kp + 1) * P_ + j]);
        wh2c[50] = wh2c[51] = __floats2half2_rn(0.f, 0.f);
    }
    __half2 wzc[32];
    if (tid < 100) {
        int j = tid % 50;
        #pragma unroll
        for (int i = 0; i < 32; i++)
            wzc[i] = __floats2half2_rn(Wh1[j * 448 + 384 + 2 * i], Wh1[j * 448 + 384 + 2 * i + 1]);
    }
    __syncthreads();

    int cb = 0;
    for (int t = t0; t < t1; t++) {
        const long bt0v = (long)r0 * T_ + t, bt1v = bt0v + T_;
        float e = 0.f;
        if (tid < 128) e = noise[((tid >> 6) ? bt1v : bt0v) * L_ + (tid & 63)];

        // ---- s1: 300 threads, one full-K dot per (row, r); w row broadcast on lane pairs ----
        if (tid < 300) {
            int r = tid & 1, row = tid >> 1;          // row 0..149
            int m = row / 50, j = row - m * 50;
            long bt = r ? bt1v : bt0v;
            const ull2* w = (const ull2*)(sW1 + row * WS);
            const ull2* h = (const ull2*)(sH + (cb * 2 + r) * WS);
            u64 aA = 0, aB = 0;
            #pragma unroll 8
            for (int k = 0; k < 64; k++) {
                ull2 wv = w[k], hv = h[k];
                aA = f2fma(wv.x, hv.x, aA);
                aB = f2fma(wv.y, hv.y, aB);
            }
            const float* pre = (m == 0) ? g_preQM : (m == 1) ? g_preQL : g_preH;
            float s = pre[bt * P_ + j] + hsum(aA) + hsum(aB);
            if (m == 0)      sA1[j * 4 + 2 * r]     = fmaxf(s, 0.f);
            else if (m == 1) sA1[j * 4 + 2 * r + 1] = fmaxf(s, 0.f);
            else             sVH[r * 52 + j] = s;
        }
        __syncthreads();

        // ---- s2: 128 threads compute; threads 128+ store h history (sH[cb] stable) ----
        if (tid < 128) {
            int r = tid >> 6, n = tid & 63;
            long bt = r ? bt1v : bt0v;
            u64 acc = pk(sb2[2 * n], sb2[2 * n + 1]);
            const u64* wp = (const u64*)(sW2t + 2 * n);
            const u64* ap = (const u64*)(sA1 + 2 * r);
            #pragma unroll 10
            for (int j = 0; j < 50; j++)
                acc = f2fma(wp[j * 64], ap[j * 2], acc);
            float2 q = up(acc);
            out[QMU_OFF + bt * L_ + n] = q.x;
            out[QLV_OFF + bt * L_ + n] = q.y;
            float z = q.x + __expf(0.5f * q.y) * e;
            sZ[r * 68 + n] = z;
            g_Z[bt * L_ + n] = z;
        } else {
            for (int idx = tid - 128; idx < 2 * H_; idx += NT - 128) {
                int r = idx >> 8, k = idx & 255;
                g_H[(r ? bt1v : bt0v) * H_ + k] = sH[(cb * 2 + r) * WS + k];
            }
        }
        __syncthreads();

        // ---- s3: add z-part (reg fp16 Wz), relu ----
        if (tid < 100) {
            int r = tid / 50, j = tid - r * 50;
            const float4* z4 = (const float4*)(sZ + r * 68);
            u64 acc1 = 0, acc2 = 0;
            #pragma unroll
            for (int i = 0; i < 16; i++) {
                float4 z = z4[i];
                float2 wa = __half22float2(wzc[2 * i]);
                float2 wb = __half22float2(wzc[2 * i + 1]);
                acc1 = f2fma(pk(wa.x, wa.y), pk(z.x, z.y), acc1);
                acc2 = f2fma(pk(wb.x, wb.y), pk(z.z, z.w), acc2);
            }
            sAH[r * 52 + j] = fmaxf(sVH[r * 52 + j] + hsum(acc1) + hsum(acc2), 0.f);
        }
        __syncthreads();

        // ---- s4: 256 threads, 2 h-outputs each (reg fp16 Wh2) ----
        if (tid < 256) {
            int r = tid >> 7, kp = tid & 127;
            const float4* a4 = (const float4*)(sAH + r * 52);
            float2 bb = *(const float2*)(sbh2 + 2 * kp);
            u64 acc = pk(bb.x, bb.y), acc2 = 0;
            #pragma unroll
            for (int q = 0; q < 13; q++) {
                float4 av = a4[q];
                float2 w0 = __half22float2(wh2c[4 * q]);     acc  = f2fma(pk(w0.x, w0.y), pk(av.x, av.x), acc);
                float2 w1 = __half22float2(wh2c[4 * q + 1]); acc2 = f2fma(pk(w1.x, w1.y), pk(av.y, av.y), acc2);
                float2 w2 = __half22float2(wh2c[4 * q + 2]); acc  = f2fma(pk(w2.x, w2.y), pk(av.z, av.z), acc);
                float2 w3 = __half22float2(wh2c[4 * q + 3]); acc2 = f2fma(pk(w3.x, w3.y), pk(av.w, av.w), acc2);
            }
            float2 r1 = up(acc), r2 = up(acc2);
            int nb = cb ^ 1;
            *(float2*)(sH + (nb * 2 + r) * WS + 2 * kp) = make_float2(r1.x + r2.x, r1.y + r2.y);
        }
        __syncthreads();
        cb ^= 1;
    }

    if (t1 < T_) {
        for (int idx = tid; idx < 2 * H_; idx += NT) {
            int r = idx >> 8, k = idx & 255;
            g_H[((long)(r0 + r) * T_ + t1) * H_ + k] = sH[(cb * 2 + r) * WS + k];
        }
    }
}

// ===================== Phase C1 (chunked) =====================
constexpr int ROWS_P = 32;
constexpr int PO_W2 = 0, PO_B1 = PO_W2 + 2 * L_ * P_, PO_B2 = PO_B1 + 128;
constexpr int PO_H = PO_B2 + 128, PO_A = PO_H + ROWS_P * WS;
constexpr size_t SMEM_P = (size_t)(PO_A + 2 * ROWS_P * 52) * sizeof(float);

__global__ __launch_bounds__(256) void k_pbranch(
    const float* __restrict__ Wpm1, const float* __restrict__ bpm1,
    const float* __restrict__ Wpm2, const float* __restrict__ bpm2,
    const float* __restrict__ Wpl1, const float* __restrict__ bpl1,
    const float* __restrict__ Wpl2, const float* __restrict__ bpl2,
    float* __restrict__ out, int t0)
{
    extern __shared__ float sm[];
    float* sW2 = sm + PO_W2; float* sb1 = sm + PO_B1;
    float* sb2 = sm + PO_B2; float* sh = sm + PO_H; float* sa = sm + PO_A;
    const int tid = threadIdx.x;
    const int b = blockIdx.x >> 2, seg = blockIdx.x & 3;
    const long bt0 = (long)b * T_ + t0 + seg * ROWS_P;

    for (int idx = tid; idx < L_ * P_; idx += 256) {
        sW2[idx] = Wpm2[idx]; sW2[L_ * P_ + idx] = Wpl2[idx];
    }
    if (tid < P_) { sb1[tid] = bpm1[tid]; sb1[64 + tid] = bpl1[tid]; }
    if (tid < L_) { sb2[tid] = bpm2[tid]; sb2[64 + tid] = bpl2[tid]; }
    for (int idx = tid; idx < ROWS_P * H_; idx += 256)
        sh[(idx >> 8) * WS + (idx & 255)] = g_H[bt0 * H_ + idx];
    __syncthreads();

    if (tid < 100) {
        int op = tid >> 2, g = tid & 3;
        const ull2* w4[4]; const ull2* h4[8];
        #pragma unroll
        for (int q = 0; q < 4; q++) {
            int o = op * 4 + q, m = o / P_, j = o - m * P_;
            w4[q] = (const ull2*)((m == 0 ? Wpm1 : Wpl1) + j * H_);
        }
        #pragma unroll
        for (int rr = 0; rr < 8; rr++) h4[rr] = (const ull2*)(sh + (rr * 4 + g) * WS);
        u64 acc[4][8];
        #pragma unroll
        for (int q = 0; q < 4; q++)
            #pragma unroll
            for (int rr = 0; rr < 8; rr++) acc[q][rr] = 0;
        #pragma unroll 4
        for (int k = 0; k < H_ / 4; k++) {
            ull2 hv[8];
            #pragma unroll
            for (int rr = 0; rr < 8; rr++) hv[rr] = h4[rr][k];
            #pragma unroll
            for (int q = 0; q < 4; q++) {
                ull2 wv = w4[q][k];
                #pragma unroll
                for (int rr = 0; rr < 8; rr++) {
                    acc[q][rr] = f2fma(wv.x, hv[rr].x, acc[q][rr]);
                    acc[q][rr] = f2fma(wv.y, hv[rr].y, acc[q][rr]);
                }
            }
        }
        #pragma unroll
        for (int q = 0; q < 4; q++) {
            int o = op * 4 + q, m = o / P_, j = o - m * P_;
            float bias = sb1[m * 64 + j];
            #pragma unroll
            for (int rr = 0; rr < 8; rr++)
                sa[(m * ROWS_P + rr * 4 + g) * 52 + j] = fmaxf(bias + hsum(acc[q][rr]), 0.f);
        }
    }
    __syncthreads();

    for (int task = tid; task < 2 * ROWS_P * L_; task += 256) {
        int m = task / (ROWS_P * L_); int rn = task - m * ROWS_P * L_;
        int r = rn >> 6, n = rn & 63;
        const float* w = sW2 + (m * L_ + n) * P_;
        const float* a = sa + (m * ROWS_P + r) * 52;
        float acc = sb2[m * 64 + n];
        #pragma unroll
        for (int j = 0; j < P_; j++) acc += w[j] * a[j];
        out[((m == 0) ? PMU_OFF : PLV_OFF) + (bt0 + r) * L_ + n] = acc;
    }
}

// ===================== Phase C2 (chunked) =====================
constexpr int ROWS_O = 32;
constexpr int OO_H = 0, OO_Z = OO_H + ROWS_O * WS, OO_B = OO_Z + ROWS_O * 68;
constexpr size_t SMEM_O = (size_t)(OO_B + 128) * sizeof(float);

__global__ __launch_bounds__(128) void k_out(
    const float* __restrict__ Wo, const float* __restrict__ bo, float* __restrict__ out, int t0)
{
    extern __shared__ float sm[];
    float* sh = sm + OO_H; float* sz = sm + OO_Z; float* sbo = sm + OO_B;
    const int tid = threadIdx.x;
    const int b = blockIdx.x >> 2, seg = blockIdx.x & 3;
    const long bt0 = (long)b * T_ + t0 + seg * ROWS_O;

    for (int idx = tid; idx < ROWS_O * H_; idx += 128)
        sh[(idx >> 8) * WS + (idx & 255)] = g_H[bt0 * H_ + idx];
    for (int idx = tid; idx < ROWS_O * L_; idx += 128)
        sz[(idx >> 6) * 68 + (idx & 63)] = g_Z[bt0 * L_ + idx];
    if (tid < I_) sbo[tid] = bo[tid];
    __syncthreads();

    {
        int ig = tid >> 2, g = tid & 3;
        const ull2* w4[4]; const ull2* h4[8]; const ull2* z4[8];
        #pragma unroll
        for (int q = 0; q < 4; q++) w4[q] = (const ull2*)(Wo + (ig * 4 + q) * 320);
        #pragma unroll
        for (int rr = 0; rr < 8; rr++) {
            h4[rr] = (const ull2*)(sh + (rr * 4 + g) * WS);
            z4[rr] = (const ull2*)(sz + (rr * 4 + g) * 68);
        }
        u64 acc[4][8];
        #pragma unroll
        for (int q = 0; q < 4; q++)
            #pragma unroll
            for (int rr = 0; rr < 8; rr++) acc[q][rr] = 0;
        #pragma unroll 4
        for (int k = 0; k < H_ / 4; k++) {
            ull2 hv[8];
            #pragma unroll
            for (int rr = 0; rr < 8; rr++) hv[rr] = h4[rr][k];
            #pragma unroll
            for (int q = 0; q < 4; q++) {
                ull2 wv = w4[q][k];
                #pragma unroll
                for (int rr = 0; rr < 8; rr++) {
                    acc[q][rr] = f2fma(wv.x, hv[rr].x, acc[q][rr]);
                    acc[q][rr] = f2fma(wv.y, hv[rr].y, acc[q][rr]);
                }
            }
        }
        #pragma unroll
        for (int k = 0; k < L_ / 4; k++) {
            ull2 zv[8];
            #pragma unroll
            for (int rr = 0; rr < 8; rr++) zv[rr] = z4[rr][k];
            #pragma unroll
            for (int q = 0; q < 4; q++) {
                ull2 wv = w4[q][64 + k];
                #pragma unroll
                for (int rr = 0; rr < 8; rr++) {
                    acc[q][rr] = f2fma(wv.x, zv[rr].x, acc[q][rr]);
                    acc[q][rr] = f2fma(wv.y, zv[rr].y, acc[q][rr]);
                }
            }
        }
        #pragma unroll
        for (int q = 0; q < 4; q++) {
            int i = ig * 4 + q; float bias = sbo[i];
            #pragma unroll
            for (int rr = 0; rr < 8; rr++) {
                float v = bias + hsum(acc[q][rr]);
                out[(bt0 + rr * 4 + g) * I_ + i] = 1.0f / (1.0f + __expf(-v));
            }
        }
    }
}

// ===================== launch: pipelined chunks =====================
extern "C" void kernel_launch(void* const* d_in, const int* in_sizes, int n_in,
                              void* d_out, int out_size) {
    const float* x = (const float*)d_in[0];
    const float* hidden = (const float*)d_in[1];
    const float* noise = (const float*)d_in[2];
    const float* Wpm1 = (const float*)d_in[3];  const float* bpm1 = (const float*)d_in[4];
    const float* Wpm2 = (const float*)d_in[5];  const float* bpm2 = (const float*)d_in[6];
    const float* Wpl1 = (const float*)d_in[7];  const float* bpl1 = (const float*)d_in[8];
    const float* Wpl2 = (const float*)d_in[9];  const float* bpl2 = (const float*)d_in[10];
    const float* Wqm1 = (const float*)d_in[11]; const float* bqm1 = (const float*)d_in[12];
    const float* Wqm2 = (const float*)d_in[13]; const float* bqm2 = (const float*)d_in[14];
    const float* Wql1 = (const float*)d_in[15]; const float* bql1 = (const float*)d_in[16];
    const float* Wql2 = (const float*)d_in[17]; const float* bql2 = (const float*)d_in[18];
    const float* Wh1 = (const float*)d_in[19];  const float* bh1 = (const float*)d_in[20];
    const float* Wh2 = (const float*)d_in[21];  const float* bh2 = (const float*)d_in[22];
    const float* Wo = (const float*)d_in[23];   const float* bo = (const float*)d_in[24];
    float* out = (float*)d_out;

    cudaFuncSetAttribute(k_pre, cudaFuncAttributeMaxDynamicSharedMemorySize, (int)SMEM_PRE);
    cudaFuncSetAttribute(k_seq, cudaFuncAttributeMaxDynamicSharedMemorySize, (int)SMEM_SEQ);
    cudaFuncSetAttribute(k_pbranch, cudaFuncAttributeMaxDynamicSharedMemorySize, (int)SMEM_P);
    cudaFuncSetAttribute(k_out, cudaFuncAttributeMaxDynamicSharedMemorySize, (int)SMEM_O);

    cudaStream_t s1;
    cudaStreamCreateWithFlags(&s1, cudaStreamNonBlocking);
    cudaEvent_t evA[NCHUNK], evB;
    for (int c = 0; c < NCHUNK; c++) cudaEventCreateWithFlags(&evA[c], cudaEventDisableTiming);
    cudaEventCreateWithFlags(&evB, cudaEventDisableTiming);

    k_pre<<<(int)(BT / ROWS_A), 256, SMEM_PRE>>>(x, Wqm1, bqm1, Wql1, bql1, Wh1, bh1);

    const int gridC = B_ * (CHUNK / ROWS_P);
    for (int c = 0; c < NCHUNK; c++) {
        int t0 = c * CHUNK, t1 = t0 + CHUNK;
        k_seq<<<B_ / 2, NT, SMEM_SEQ>>>(hidden, noise, Wqm1, Wqm2, bqm2,
                                        Wql1, Wql2, bql2, Wh1, Wh2, bh2, out, t0, t1);
        cudaEventRecord(evA[c], 0);
        cudaStreamWaitEvent(s1, evA[c], 0);
        k_pbranch<<<gridC, 256, SMEM_P, s1>>>(Wpm1, bpm1, Wpm2, bpm2,
                                              Wpl1, bpl1, Wpl2, bpl2, out, t0);
        k_out<<<gridC, 128, SMEM_O, s1>>>(Wo, bo, out, t0);
    }
    cudaEventRecord(evB, s1);
    cudaStreamWaitEvent(0, evB, 0);
}